// round 1
// baseline (speedup 1.0000x reference)
#include <cuda_runtime.h>
#include <math.h>

#define NB 4
#define NC 256
#define NH 48
#define NW 48
#define SL 2304
#define NHEADS 8
#define NHD 32
#define SG 144
#define HC2 12
#define WC2 12

// ---------------- scratch (no allocations allowed) ----------------
__device__ float g_qkv_l[NB * 3 * NC * SL];   // 28.3 MB
__device__ float g_attn_l[NB * NC * SL];
__device__ float g_local [NB * NC * SL];
__device__ float g_f1a   [NB * NC * SL];
__device__ float g_hbuf  [NB * NC * SL];
__device__ float g_xc    [NB * NC * SG];
__device__ float g_qkv_g [NB * 3 * NC * SG];
__device__ float g_attn_g[NB * NC * SG];
__device__ float g_gs    [NB * NC * SG];
__device__ float g_gt    [NB * NC * SG];

// ---------------- generic tiled GEMM: Y[b,o,s] = sum_c W[o,c]*X[b,c,s] (+bias) ----------------
// grid: (ceil(S/64), O/64, B), block 256.  W row stride = ldw (supports w_f1 column slices).
__global__ __launch_bounds__(256) void gemm_ws(
    const float* __restrict__ Wm, const float* __restrict__ X,
    float* __restrict__ Y, const float* __restrict__ bias,
    int O, int Cin, int ldw, int Ssz)
{
    __shared__ float Ws[16][68];   // [k][o]
    __shared__ float Xs[16][68];   // [k][s]
    int tid = threadIdx.x;
    int tx = tid & 15, ty = tid >> 4;
    int s0 = blockIdx.x * 64, o0 = blockIdx.y * 64, b = blockIdx.z;
    const float* Xb = X + (size_t)b * Cin * Ssz;

    float acc[4][4];
    #pragma unroll
    for (int i = 0; i < 4; i++)
        #pragma unroll
        for (int j = 0; j < 4; j++) acc[i][j] = 0.f;

    for (int c0 = 0; c0 < Cin; c0 += 16) {
        // W tile: 64 o-rows x 16 k  (float4 per thread)
        {
            int row = tid >> 2, kk = (tid & 3) * 4;
            const float4 w4 = *reinterpret_cast<const float4*>(
                Wm + (size_t)(o0 + row) * ldw + c0 + kk);
            Ws[kk + 0][row] = w4.x; Ws[kk + 1][row] = w4.y;
            Ws[kk + 2][row] = w4.z; Ws[kk + 3][row] = w4.w;
        }
        // X tile: 16 k x 64 s (coalesced along s)
        #pragma unroll
        for (int i = 0; i < 4; i++) {
            int idx = tid + i * 256;
            int k = idx >> 6, s = idx & 63;
            float v = 0.f;
            if (s0 + s < Ssz) v = Xb[(size_t)(c0 + k) * Ssz + s0 + s];
            Xs[k][s] = v;
        }
        __syncthreads();
        #pragma unroll
        for (int k = 0; k < 16; k++) {
            float a0 = Ws[k][4 * ty + 0], a1 = Ws[k][4 * ty + 1];
            float a2 = Ws[k][4 * ty + 2], a3 = Ws[k][4 * ty + 3];
            float b0 = Xs[k][4 * tx + 0], b1 = Xs[k][4 * tx + 1];
            float b2 = Xs[k][4 * tx + 2], b3 = Xs[k][4 * tx + 3];
            acc[0][0] += a0 * b0; acc[0][1] += a0 * b1; acc[0][2] += a0 * b2; acc[0][3] += a0 * b3;
            acc[1][0] += a1 * b0; acc[1][1] += a1 * b1; acc[1][2] += a1 * b2; acc[1][3] += a1 * b3;
            acc[2][0] += a2 * b0; acc[2][1] += a2 * b1; acc[2][2] += a2 * b2; acc[2][3] += a2 * b3;
            acc[3][0] += a3 * b0; acc[3][1] += a3 * b1; acc[3][2] += a3 * b2; acc[3][3] += a3 * b3;
        }
        __syncthreads();
    }

    float* Yb = Y + (size_t)b * O * Ssz;
    #pragma unroll
    for (int r = 0; r < 4; r++) {
        int o = o0 + 4 * ty + r;
        float bv = bias ? bias[o] : 0.f;
        #pragma unroll
        for (int c = 0; c < 4; c++) {
            int s = s0 + 4 * tx + c;
            if (s < Ssz) Yb[(size_t)o * Ssz + s] = acc[r][c] + bv;
        }
    }
}

// ---------------- flash attention (fp32, online softmax) ----------------
// qkv layout: [b][g*256 + h*32 + d][s]  (g: 0=q,1=k,2=v).  out: [b][h*32+d][s].
// L2 norm of q,k over d and the hd^-0.5 scale are fused into the tile loads.
// grid (ceil(S/64), heads, B), block 256.
__global__ __launch_bounds__(256) void flash_attn(
    const float* __restrict__ qkv, float* __restrict__ out, int Ssz)
{
    __shared__ __align__(16) float Qs[64][33];
    __shared__ __align__(16) float Ks[64][33];
    __shared__ __align__(16) float Vs[64][36];
    __shared__ __align__(16) float Ss[64][65];
    __shared__ float Pm[4][64];

    int tid = threadIdx.x;
    int qt = blockIdx.x, hh = blockIdx.y, bb = blockIdx.z;
    int s0 = qt * 64;
    const float* qb = qkv + ((size_t)bb * 3 * NC + 0 * NC + hh * NHD) * Ssz;
    const float* kb = qkv + ((size_t)bb * 3 * NC + 1 * NC + hh * NHD) * Ssz;
    const float* vb = qkv + ((size_t)bb * 3 * NC + 2 * NC + hh * NHD) * Ssz;

    // load + transpose Q tile
    for (int idx = tid; idx < 64 * 32; idx += 256) {
        int d = idx >> 6, col = idx & 63;
        float v = (s0 + col < Ssz) ? qb[(size_t)d * Ssz + s0 + col] : 0.f;
        Qs[col][d] = v;
    }
    __syncthreads();
    const float SCALE = 0.17677669529663687f;  // 32^-0.5
    if (tid < 64) {
        float ss = 0.f;
        #pragma unroll
        for (int d = 0; d < 32; d++) { float v = Qs[tid][d]; ss += v * v; }
        float f = SCALE / fmaxf(sqrtf(ss), 1e-12f);
        #pragma unroll
        for (int d = 0; d < 32; d++) Qs[tid][d] *= f;
    }

    int tx = tid & 15, ty = tid >> 4;   // phase A roles
    int r  = tid & 63, seg = tid >> 6;  // phase B roles
    int dch = seg * 8;

    float m = -1e30f, l = 0.f;
    float Ov[8];
    #pragma unroll
    for (int i = 0; i < 8; i++) Ov[i] = 0.f;

    int nkt = (Ssz + 63) / 64;
    for (int kt = 0; kt < nkt; kt++) {
        int k0 = kt * 64;
        __syncthreads();  // protect Qs norm (iter0) / Ks,Vs,Ss of prev iter
        for (int idx = tid; idx < 64 * 32; idx += 256) {
            int d = idx >> 6, col = idx & 63;
            bool ok = (k0 + col < Ssz);
            Ks[col][d] = ok ? kb[(size_t)d * Ssz + k0 + col] : 0.f;
            Vs[col][d] = ok ? vb[(size_t)d * Ssz + k0 + col] : 0.f;
        }
        __syncthreads();
        if (tid < 64) {
            float ss = 0.f;
            #pragma unroll
            for (int d = 0; d < 32; d++) { float v = Ks[tid][d]; ss += v * v; }
            float f = 1.f / fmaxf(sqrtf(ss), 1e-12f);
            #pragma unroll
            for (int d = 0; d < 32; d++) Ks[tid][d] *= f;
        }
        __syncthreads();

        // ---- phase A: scores 64x64 (Q already carries the softmax scale) ----
        float acc[4][4];
        #pragma unroll
        for (int i = 0; i < 4; i++)
            #pragma unroll
            for (int j = 0; j < 4; j++) acc[i][j] = 0.f;
        #pragma unroll 8
        for (int d = 0; d < 32; d++) {
            float q0 = Qs[4 * ty + 0][d], q1 = Qs[4 * ty + 1][d];
            float q2 = Qs[4 * ty + 2][d], q3 = Qs[4 * ty + 3][d];
            float k0v = Ks[4 * tx + 0][d], k1v = Ks[4 * tx + 1][d];
            float k2v = Ks[4 * tx + 2][d], k3v = Ks[4 * tx + 3][d];
            acc[0][0] += q0 * k0v; acc[0][1] += q0 * k1v; acc[0][2] += q0 * k2v; acc[0][3] += q0 * k3v;
            acc[1][0] += q1 * k0v; acc[1][1] += q1 * k1v; acc[1][2] += q1 * k2v; acc[1][3] += q1 * k3v;
            acc[2][0] += q2 * k0v; acc[2][1] += q2 * k1v; acc[2][2] += q2 * k2v; acc[2][3] += q2 * k3v;
            acc[3][0] += q3 * k0v; acc[3][1] += q3 * k1v; acc[3][2] += q3 * k2v; acc[3][3] += q3 * k3v;
        }
        #pragma unroll
        for (int rr = 0; rr < 4; rr++)
            #pragma unroll
            for (int cc = 0; cc < 4; cc++) {
                int kc = k0 + 4 * tx + cc;
                Ss[4 * ty + rr][4 * tx + cc] = (kc < Ssz) ? acc[rr][cc] : -1e30f;
            }
        __syncthreads();

        // ---- phase B: online softmax ----
        float pm = -1e30f;
        #pragma unroll
        for (int j = 0; j < 16; j++) pm = fmaxf(pm, Ss[r][seg * 16 + j]);
        Pm[seg][r] = pm;
        __syncthreads();
        float rowmax = fmaxf(fmaxf(Pm[0][r], Pm[1][r]), fmaxf(Pm[2][r], Pm[3][r]));
        float mnew = fmaxf(m, rowmax);
        float corr = __expf(m - mnew);
        __syncthreads();  // Pm reads done before overwrite
        float lp = 0.f;
        #pragma unroll
        for (int j = 0; j < 16; j++) {
            float p = __expf(Ss[r][seg * 16 + j] - mnew);
            Ss[r][seg * 16 + j] = p;
            lp += p;
        }
        Pm[seg][r] = lp;
        __syncthreads();
        float lsum = Pm[0][r] + Pm[1][r] + Pm[2][r] + Pm[3][r];
        l = l * corr + lsum;
        m = mnew;
        #pragma unroll
        for (int i = 0; i < 8; i++) Ov[i] *= corr;

        // ---- PV: O[r][dch..dch+7] += p_j * V[j][dch..] ----
        #pragma unroll 4
        for (int j = 0; j < 64; j++) {
            float p = Ss[r][j];
            float4 v0 = *reinterpret_cast<const float4*>(&Vs[j][dch]);
            float4 v1 = *reinterpret_cast<const float4*>(&Vs[j][dch + 4]);
            Ov[0] += p * v0.x; Ov[1] += p * v0.y; Ov[2] += p * v0.z; Ov[3] += p * v0.w;
            Ov[4] += p * v1.x; Ov[5] += p * v1.y; Ov[6] += p * v1.z; Ov[7] += p * v1.w;
        }
    }

    __syncthreads();
    float inv = 1.f / l;
    #pragma unroll
    for (int i = 0; i < 8; i++) Ss[r][dch + i] = Ov[i] * inv;
    __syncthreads();
    float* ob = out + ((size_t)bb * NC + hh * NHD) * Ssz;
    for (int idx = tid; idx < 64 * 32; idx += 256) {
        int d = idx >> 6, col = idx & 63;
        if (s0 + col < Ssz) ob[(size_t)d * Ssz + s0 + col] = Ss[col][d];
    }
}

// ---------------- 4x4 avg pool ----------------
__global__ void avgpool4(const float* __restrict__ x, float* __restrict__ xc) {
    int idx = blockIdx.x * blockDim.x + threadIdx.x;
    if (idx >= NB * NC * SG) return;
    int wc = idx % WC2;
    int hc = (idx / WC2) % HC2;
    int bc = idx / SG;
    const float* xp = x + (size_t)bc * (NH * NW) + (hc * 4) * NW + wc * 4;
    float s = 0.f;
    #pragma unroll
    for (int di = 0; di < 4; di++)
        #pragma unroll
        for (int dj = 0; dj < 4; dj++) s += xp[di * NW + dj];
    xc[idx] = s * (1.f / 16.f);
}

// ---------------- h = GELU(f1a + bilinear_up(gt) + b_f1) ----------------
// bilinear(12->48) commutes with the 1x1 conv, so gt is conv'd at S=144 and upsampled here.
__global__ void fuse_gelu(const float* __restrict__ f1a, const float* __restrict__ gt,
                          const float* __restrict__ b1, float* __restrict__ h) {
    int idx = blockIdx.x * blockDim.x + threadIdx.x;
    if (idx >= NB * NC * SL) return;
    int p = idx % SL;
    int bc = idx / SL;
    int o = bc % NC;
    int i = p / NW, j = p % NW;
    float si = (i + 0.5f) * 0.25f - 0.5f;
    float sj = (j + 0.5f) * 0.25f - 0.5f;
    float fi = floorf(si), fj = floorf(sj);
    float wi = si - fi, wj = sj - fj;
    int i0 = (int)fi, j0 = (int)fj;
    int ia = min(max(i0, 0), HC2 - 1), ib = min(max(i0 + 1, 0), HC2 - 1);
    int ja = min(max(j0, 0), WC2 - 1), jb = min(max(j0 + 1, 0), WC2 - 1);
    const float* gp = gt + (size_t)bc * SG;
    float g00 = gp[ia * WC2 + ja], g01 = gp[ia * WC2 + jb];
    float g10 = gp[ib * WC2 + ja], g11 = gp[ib * WC2 + jb];
    float gv = (1.f - wi) * ((1.f - wj) * g00 + wj * g01)
             + wi * ((1.f - wj) * g10 + wj * g11);
    float v = f1a[idx] + gv + b1[o];
    h[idx] = 0.5f * v * (1.f + erff(v * 0.70710678118654752f));
}

// ---------------- launch ----------------
extern "C" void kernel_launch(void* const* d_in, const int* in_sizes, int n_in,
                              void* d_out, int out_size) {
    const float* x        = (const float*)d_in[0];
    const float* w_qkv_l  = (const float*)d_in[1];
    const float* w_proj_l = (const float*)d_in[2];
    const float* b_proj_l = (const float*)d_in[3];
    const float* w_qkv_g  = (const float*)d_in[4];
    const float* w_proj_g = (const float*)d_in[5];
    const float* b_proj_g = (const float*)d_in[6];
    const float* w_f1     = (const float*)d_in[7];
    const float* b_f1     = (const float*)d_in[8];
    const float* w_f2     = (const float*)d_in[9];
    const float* b_f2     = (const float*)d_in[10];
    float* out = (float*)d_out;

    float *qkv_l, *attn_l, *local, *f1a, *h, *xc, *qkv_g, *attn_g, *gs, *gt;
    cudaGetSymbolAddress((void**)&qkv_l,  g_qkv_l);
    cudaGetSymbolAddress((void**)&attn_l, g_attn_l);
    cudaGetSymbolAddress((void**)&local,  g_local);
    cudaGetSymbolAddress((void**)&f1a,    g_f1a);
    cudaGetSymbolAddress((void**)&h,      g_hbuf);
    cudaGetSymbolAddress((void**)&xc,     g_xc);
    cudaGetSymbolAddress((void**)&qkv_g,  g_qkv_g);
    cudaGetSymbolAddress((void**)&attn_g, g_attn_g);
    cudaGetSymbolAddress((void**)&gs,     g_gs);
    cudaGetSymbolAddress((void**)&gt,     g_gt);

    dim3 blk(256);

    // local branch
    gemm_ws<<<dim3(SL / 64, 768 / 64, NB), blk>>>(w_qkv_l, x, qkv_l, nullptr, 768, 256, 256, SL);
    flash_attn<<<dim3(SL / 64, NHEADS, NB), blk>>>(qkv_l, attn_l, SL);
    gemm_ws<<<dim3(SL / 64, 4, NB), blk>>>(w_proj_l, attn_l, local, b_proj_l, 256, 256, 256, SL);

    // global branch (S=144)
    avgpool4<<<(NB * NC * SG + 255) / 256, blk>>>(x, xc);
    gemm_ws<<<dim3(3, 12, NB), blk>>>(w_qkv_g, xc, qkv_g, nullptr, 768, 256, 256, SG);
    flash_attn<<<dim3(3, NHEADS, NB), blk>>>(qkv_g, attn_g, SG);
    gemm_ws<<<dim3(3, 4, NB), blk>>>(w_proj_g, attn_g, gs, b_proj_g, 256, 256, 256, SG);

    // f1 split: local half at S=2304, global half at S=144 (upsample after conv)
    gemm_ws<<<dim3(SL / 64, 4, NB), blk>>>(w_f1, local, f1a, nullptr, 256, 256, 512, SL);
    gemm_ws<<<dim3(3, 4, NB), blk>>>(w_f1 + 256, gs, gt, nullptr, 256, 256, 512, SG);
    fuse_gelu<<<(NB * NC * SL + 255) / 256, blk>>>(f1a, gt, b_f1, h);

    // f2 -> output
    gemm_ws<<<dim3(SL / 64, 4, NB), blk>>>(w_f2, h, out, b_f2, 256, 256, 256, SL);
}

// round 4
// speedup vs baseline: 2.4409x; 2.4409x over previous
#include <cuda_runtime.h>
#include <math.h>

#define NB 4
#define NC 256
#define NH 48
#define NW 48
#define SL 2304
#define NHEADS 8
#define NHD 32
#define SG 144
#define HC2 12
#define WC2 12

// ---------------- scratch (no allocations allowed) ----------------
__device__ float g_qkv_l[NB * 3 * NC * SL];
__device__ float g_attn_l[NB * NC * SL];
__device__ float g_local [NB * NC * SL];
__device__ float g_f1a   [NB * NC * SL];
__device__ float g_hbuf  [NB * NC * SL];
__device__ float g_xc    [NB * NC * SG];
__device__ float g_qkv_g [NB * 3 * NC * SG];
__device__ float g_attn_g[NB * NC * SG];
__device__ float g_gs    [NB * NC * SG];
__device__ float g_gt    [NB * NC * SG];

// ---------------- tf32 helpers ----------------
__device__ __forceinline__ unsigned f2tf(float x) {
    unsigned r; asm("cvt.rna.tf32.f32 %0, %1;" : "=r"(r) : "f"(x)); return r;
}
__device__ __forceinline__ void mma8(float& c0, float& c1, float& c2, float& c3,
                                     unsigned a0, unsigned a1, unsigned a2, unsigned a3,
                                     unsigned b0, unsigned b1) {
    asm volatile("mma.sync.aligned.m16n8k8.row.col.f32.tf32.tf32.f32 "
                 "{%0,%1,%2,%3},{%4,%5,%6,%7},{%8,%9},{%0,%1,%2,%3};"
                 : "+f"(c0), "+f"(c1), "+f"(c2), "+f"(c3)
                 : "r"(a0), "r"(a1), "r"(a2), "r"(a3), "r"(b0), "r"(b1));
}

// ---------------- tf32 tensor-core GEMM: Y[b,o,s] = sum_c W[o,c]*X[b,c,s] (+bias) ----------------
// block tile 64(o) x 128(s), k-chunk 16, 8 warps as 2(o) x 4(s), warp tile 32x32.
__global__ __launch_bounds__(256) void gemm_tc(
    const float* __restrict__ Wm, const float* __restrict__ X,
    float* __restrict__ Y, const float* __restrict__ bias,
    int O, int Cin, int ldw, int Ssz)
{
    __shared__ unsigned Ws[64][20];   // [o][k]  pad 20 -> frag loads conflict-free
    __shared__ unsigned Xs[16][136];  // [k][s]  pad 136 -> frag loads conflict-free
    int tid = threadIdx.x;
    int wid = tid >> 5, lane = tid & 31;
    int g = lane >> 2, tc = lane & 3;
    int wm = wid & 1, wn = wid >> 1;
    int s0 = blockIdx.x * 128, o0 = blockIdx.y * 64, b = blockIdx.z;
    const float* Xb = X + (size_t)b * Cin * Ssz;
    bool sfull = (s0 + 128 <= Ssz);

    float C[2][4][4];
    #pragma unroll
    for (int mt = 0; mt < 2; mt++)
        #pragma unroll
        for (int nt = 0; nt < 4; nt++)
            #pragma unroll
            for (int i = 0; i < 4; i++) C[mt][nt][i] = 0.f;

    for (int c0 = 0; c0 < Cin; c0 += 16) {
        {   // W tile 64x16
            int row = tid >> 2, kk = (tid & 3) << 2;
            float4 w4 = *reinterpret_cast<const float4*>(Wm + (size_t)(o0 + row) * ldw + c0 + kk);
            Ws[row][kk + 0] = f2tf(w4.x); Ws[row][kk + 1] = f2tf(w4.y);
            Ws[row][kk + 2] = f2tf(w4.z); Ws[row][kk + 3] = f2tf(w4.w);
        }
        #pragma unroll
        for (int i = 0; i < 2; i++) {  // X tile 16x128
            int idx = tid + i * 256;
            int k = idx >> 5, s4 = (idx & 31) << 2;
            if (sfull) {
                float4 x4 = *reinterpret_cast<const float4*>(Xb + (size_t)(c0 + k) * Ssz + s0 + s4);
                Xs[k][s4 + 0] = f2tf(x4.x); Xs[k][s4 + 1] = f2tf(x4.y);
                Xs[k][s4 + 2] = f2tf(x4.z); Xs[k][s4 + 3] = f2tf(x4.w);
            } else {
                #pragma unroll
                for (int j = 0; j < 4; j++) {
                    float v = (s0 + s4 + j < Ssz) ? Xb[(size_t)(c0 + k) * Ssz + s0 + s4 + j] : 0.f;
                    Xs[k][s4 + j] = f2tf(v);
                }
            }
        }
        __syncthreads();
        #pragma unroll
        for (int ks = 0; ks < 2; ks++) {
            int kk = ks * 8;
            unsigned a[2][4], bf[4][2];
            #pragma unroll
            for (int mt = 0; mt < 2; mt++) {
                int ob = wm * 32 + mt * 16;
                a[mt][0] = Ws[ob + g][kk + tc];     a[mt][1] = Ws[ob + g + 8][kk + tc];
                a[mt][2] = Ws[ob + g][kk + tc + 4]; a[mt][3] = Ws[ob + g + 8][kk + tc + 4];
            }
            #pragma unroll
            for (int nt = 0; nt < 4; nt++) {
                int sb = wn * 32 + nt * 8;
                bf[nt][0] = Xs[kk + tc][sb + g];
                bf[nt][1] = Xs[kk + tc + 4][sb + g];
            }
            #pragma unroll
            for (int mt = 0; mt < 2; mt++)
                #pragma unroll
                for (int nt = 0; nt < 4; nt++)
                    mma8(C[mt][nt][0], C[mt][nt][1], C[mt][nt][2], C[mt][nt][3],
                         a[mt][0], a[mt][1], a[mt][2], a[mt][3], bf[nt][0], bf[nt][1]);
        }
        __syncthreads();
    }

    float* Yb = Y + (size_t)b * O * Ssz;
    #pragma unroll
    for (int mt = 0; mt < 2; mt++)
        #pragma unroll
        for (int half = 0; half < 2; half++) {
            int o = o0 + wm * 32 + mt * 16 + g + half * 8;
            float bv = bias ? bias[o] : 0.f;
            #pragma unroll
            for (int nt = 0; nt < 4; nt++) {
                int s = s0 + wn * 32 + nt * 8 + 2 * tc;
                float v0 = C[mt][nt][half * 2 + 0] + bv;
                float v1 = C[mt][nt][half * 2 + 1] + bv;
                if (s + 1 < Ssz) *reinterpret_cast<float2*>(Yb + (size_t)o * Ssz + s) = make_float2(v0, v1);
                else if (s < Ssz) Yb[(size_t)o * Ssz + s] = v0;
            }
        }
}

// ---------------- prenorm: L2-normalize q (x scale) and k rows, cvt to tf32, in place ----------------
// grid (ceil(S/128), 16, B), block 128.  blockIdx.y: h = y&7, isk = y>>3.
__global__ void prenorm(float* qkv, int Ssz) {
    int s = blockIdx.x * blockDim.x + threadIdx.x;
    if (s >= Ssz) return;
    int h = blockIdx.y & 7, isk = blockIdx.y >> 3, b = blockIdx.z;
    float* p = qkv + ((size_t)(b * 3 + isk) * NC + h * NHD) * Ssz + s;
    float v[32]; float ss = 0.f;
    #pragma unroll
    for (int d = 0; d < 32; d++) { v[d] = p[(size_t)d * Ssz]; ss += v[d] * v[d]; }
    float f = ((isk == 0) ? 0.17677669529663687f : 1.f) / fmaxf(sqrtf(ss), 1e-12f);
    #pragma unroll
    for (int d = 0; d < 32; d++) p[(size_t)d * Ssz] = __uint_as_float(f2tf(v[d] * f));
}

// cvt v section to tf32 in place: grid (ceil(NC*S/256), B)
__global__ void vcvt(float* qkv, int Ssz) {
    int i = blockIdx.x * blockDim.x + threadIdx.x;
    if (i >= NC * Ssz) return;
    float* p = qkv + (size_t)(blockIdx.y * 3 + 2) * NC * Ssz + i;
    *p = __uint_as_float(f2tf(*p));
}

// ---------------- flash attention, tf32 tensor cores ----------------
// qkv pre-normalized/tf32.  Br=128 (8 warps x 16 rows), Bc=64, d=32.
// grid (ceil(S/128), heads, B), block 256.
__global__ __launch_bounds__(256, 2) void flash_tc(
    const float* __restrict__ qkv, float* __restrict__ out, int Ssz)
{
    __shared__ unsigned Ks[64][36];  // [kv][d] pad 36 -> QK B-frags conflict-free
    __shared__ unsigned Vs[64][40];  // [kv][d] pad 40 -> PV B-frags conflict-free
    int tid = threadIdx.x, wid = tid >> 5, lane = tid & 31;
    int g = lane >> 2, tc = lane & 3;
    int qt = blockIdx.x, hh = blockIdx.y, bb = blockIdx.z;
    int s0 = qt * 128;
    const float* qb = qkv + ((size_t)bb * 3 * NC + hh * NHD) * Ssz;
    const float* kb = qb + (size_t)NC * Ssz;
    const float* vb = qb + (size_t)2 * NC * Ssz;

    // Q fragments in registers for all kv tiles
    unsigned qa[4][4];
    int r0 = s0 + wid * 16 + g, r1 = r0 + 8;
    #pragma unroll
    for (int ks = 0; ks < 4; ks++) {
        int d0 = ks * 8 + tc;
        qa[ks][0] = (r0 < Ssz) ? __float_as_uint(qb[(size_t)d0 * Ssz + r0]) : 0u;
        qa[ks][1] = (r1 < Ssz) ? __float_as_uint(qb[(size_t)d0 * Ssz + r1]) : 0u;
        qa[ks][2] = (r0 < Ssz) ? __float_as_uint(qb[(size_t)(d0 + 4) * Ssz + r0]) : 0u;
        qa[ks][3] = (r1 < Ssz) ? __float_as_uint(qb[(size_t)(d0 + 4) * Ssz + r1]) : 0u;
    }

    float m0 = -1e30f, m1 = -1e30f, l0 = 0.f, l1 = 0.f;
    float Oa[4][4];
    #pragma unroll
    for (int dt = 0; dt < 4; dt++)
        #pragma unroll
        for (int i = 0; i < 4; i++) Oa[dt][i] = 0.f;

    int src1 = (lane & ~3) | (tc >> 1);
    int src2 = src1 + 2;
    bool esel = (tc & 1);

    int nkt = (Ssz + 63) >> 6;
    for (int kt = 0; kt < nkt; kt++) {
        int k0 = kt * 64;
        __syncthreads();
        bool full = (k0 + 64 <= Ssz);
        #pragma unroll
        for (int i = 0; i < 2; i++) {
            int idx = tid + i * 256;           // 0..511
            int d = idx >> 4, c4 = (idx & 15) << 2;
            if (full) {
                float4 k4 = *reinterpret_cast<const float4*>(kb + (size_t)d * Ssz + k0 + c4);
                float4 v4 = *reinterpret_cast<const float4*>(vb + (size_t)d * Ssz + k0 + c4);
                Ks[c4 + 0][d] = __float_as_uint(k4.x); Ks[c4 + 1][d] = __float_as_uint(k4.y);
                Ks[c4 + 2][d] = __float_as_uint(k4.z); Ks[c4 + 3][d] = __float_as_uint(k4.w);
                Vs[c4 + 0][d] = __float_as_uint(v4.x); Vs[c4 + 1][d] = __float_as_uint(v4.y);
                Vs[c4 + 2][d] = __float_as_uint(v4.z); Vs[c4 + 3][d] = __float_as_uint(v4.w);
            } else {
                #pragma unroll
                for (int j = 0; j < 4; j++) {
                    int sc = k0 + c4 + j;
                    unsigned kv = 0u, vv = 0u;
                    if (sc < Ssz) {
                        kv = __float_as_uint(kb[(size_t)d * Ssz + sc]);
                        vv = __float_as_uint(vb[(size_t)d * Ssz + sc]);
                    }
                    Ks[c4 + j][d] = kv; Vs[c4 + j][d] = vv;
                }
            }
        }
        __syncthreads();

        // ---- S = Q K^T ----
        float Sf[8][4];
        #pragma unroll
        for (int nt = 0; nt < 8; nt++)
            #pragma unroll
            for (int i = 0; i < 4; i++) Sf[nt][i] = 0.f;
        #pragma unroll
        for (int ks = 0; ks < 4; ks++)
            #pragma unroll
            for (int nt = 0; nt < 8; nt++) {
                unsigned b0 = Ks[nt * 8 + g][ks * 8 + tc];
                unsigned b1 = Ks[nt * 8 + g][ks * 8 + tc + 4];
                mma8(Sf[nt][0], Sf[nt][1], Sf[nt][2], Sf[nt][3],
                     qa[ks][0], qa[ks][1], qa[ks][2], qa[ks][3], b0, b1);
            }
        if (!full) {
            #pragma unroll
            for (int nt = 0; nt < 8; nt++) {
                int c = k0 + nt * 8 + 2 * tc;
                if (c     >= Ssz) { Sf[nt][0] = -1e30f; Sf[nt][2] = -1e30f; }
                if (c + 1 >= Ssz) { Sf[nt][1] = -1e30f; Sf[nt][3] = -1e30f; }
            }
        }

        // ---- warp-local online softmax (rows g and g+8) ----
        float t0 = -1e30f, t1 = -1e30f;
        #pragma unroll
        for (int nt = 0; nt < 8; nt++) {
            t0 = fmaxf(t0, fmaxf(Sf[nt][0], Sf[nt][1]));
            t1 = fmaxf(t1, fmaxf(Sf[nt][2], Sf[nt][3]));
        }
        t0 = fmaxf(t0, __shfl_xor_sync(0xffffffffu, t0, 1));
        t0 = fmaxf(t0, __shfl_xor_sync(0xffffffffu, t0, 2));
        t1 = fmaxf(t1, __shfl_xor_sync(0xffffffffu, t1, 1));
        t1 = fmaxf(t1, __shfl_xor_sync(0xffffffffu, t1, 2));
        float mn0 = fmaxf(m0, t0), mn1 = fmaxf(m1, t1);
        float co0 = __expf(m0 - mn0), co1 = __expf(m1 - mn1);
        m0 = mn0; m1 = mn1;
        float su0 = 0.f, su1 = 0.f;
        #pragma unroll
        for (int nt = 0; nt < 8; nt++) {
            Sf[nt][0] = __expf(Sf[nt][0] - mn0); su0 += Sf[nt][0];
            Sf[nt][1] = __expf(Sf[nt][1] - mn0); su0 += Sf[nt][1];
            Sf[nt][2] = __expf(Sf[nt][2] - mn1); su1 += Sf[nt][2];
            Sf[nt][3] = __expf(Sf[nt][3] - mn1); su1 += Sf[nt][3];
        }
        su0 += __shfl_xor_sync(0xffffffffu, su0, 1);
        su0 += __shfl_xor_sync(0xffffffffu, su0, 2);
        su1 += __shfl_xor_sync(0xffffffffu, su1, 1);
        su1 += __shfl_xor_sync(0xffffffffu, su1, 2);
        l0 = l0 * co0 + su0; l1 = l1 * co1 + su1;
        #pragma unroll
        for (int dt = 0; dt < 4; dt++) {
            Oa[dt][0] *= co0; Oa[dt][1] *= co0;
            Oa[dt][2] *= co1; Oa[dt][3] *= co1;
        }

        // ---- O += P V  (P C-frag -> A-frag via warp shuffles) ----
        #pragma unroll
        for (int ks = 0; ks < 8; ks++) {
            float v00 = __shfl_sync(0xffffffffu, Sf[ks][0], src1);
            float v01 = __shfl_sync(0xffffffffu, Sf[ks][1], src1);
            float v20 = __shfl_sync(0xffffffffu, Sf[ks][2], src1);
            float v21 = __shfl_sync(0xffffffffu, Sf[ks][3], src1);
            float w00 = __shfl_sync(0xffffffffu, Sf[ks][0], src2);
            float w01 = __shfl_sync(0xffffffffu, Sf[ks][1], src2);
            float w20 = __shfl_sync(0xffffffffu, Sf[ks][2], src2);
            float w21 = __shfl_sync(0xffffffffu, Sf[ks][3], src2);
            unsigned a0 = f2tf(esel ? v01 : v00);
            unsigned a1 = f2tf(esel ? v21 : v20);
            unsigned a2 = f2tf(esel ? w01 : w00);
            unsigned a3 = f2tf(esel ? w21 : w20);
            #pragma unroll
            for (int dt = 0; dt < 4; dt++) {
                unsigned b0 = Vs[ks * 8 + tc][dt * 8 + g];
                unsigned b1 = Vs[ks * 8 + tc + 4][dt * 8 + g];
                mma8(Oa[dt][0], Oa[dt][1], Oa[dt][2], Oa[dt][3], a0, a1, a2, a3, b0, b1);
            }
        }
    }

    float i0 = 1.f / l0, i1 = 1.f / l1;
    float* ob = out + ((size_t)bb * NC + hh * NHD) * Ssz;
    #pragma unroll
    for (int dt = 0; dt < 4; dt++) {
        int d = dt * 8 + 2 * tc;
        if (r0 < Ssz) {
            ob[(size_t)d * Ssz + r0]       = Oa[dt][0] * i0;
            ob[(size_t)(d + 1) * Ssz + r0] = Oa[dt][1] * i0;
        }
        if (r1 < Ssz) {
            ob[(size_t)d * Ssz + r1]       = Oa[dt][2] * i1;
            ob[(size_t)(d + 1) * Ssz + r1] = Oa[dt][3] * i1;
        }
    }
}

// ---------------- 4x4 avg pool ----------------
__global__ void avgpool4(const float* __restrict__ x, float* __restrict__ xc) {
    int idx = blockIdx.x * blockDim.x + threadIdx.x;
    if (idx >= NB * NC * SG) return;
    int wc = idx % WC2;
    int hc = (idx / WC2) % HC2;
    int bc = idx / SG;
    const float* xp = x + (size_t)bc * (NH * NW) + (hc * 4) * NW + wc * 4;
    float s = 0.f;
    #pragma unroll
    for (int di = 0; di < 4; di++)
        #pragma unroll
        for (int dj = 0; dj < 4; dj++) s += xp[di * NW + dj];
    xc[idx] = s * (1.f / 16.f);
}

// ---------------- h = GELU(f1a + bilinear_up(gt) + b_f1) ----------------
__global__ void fuse_gelu(const float* __restrict__ f1a, const float* __restrict__ gt,
                          const float* __restrict__ b1, float* __restrict__ h) {
    int idx = blockIdx.x * blockDim.x + threadIdx.x;
    if (idx >= NB * NC * SL) return;
    int p = idx % SL;
    int bc = idx / SL;
    int o = bc % NC;
    int i = p / NW, j = p % NW;
    float si = (i + 0.5f) * 0.25f - 0.5f;
    float sj = (j + 0.5f) * 0.25f - 0.5f;
    float fi = floorf(si), fj = floorf(sj);
    float wi = si - fi, wj = sj - fj;
    int i0 = (int)fi, j0 = (int)fj;
    int ia = min(max(i0, 0), HC2 - 1), ib = min(max(i0 + 1, 0), HC2 - 1);
    int ja = min(max(j0, 0), WC2 - 1), jb = min(max(j0 + 1, 0), WC2 - 1);
    const float* gp = gt + (size_t)bc * SG;
    float g00 = gp[ia * WC2 + ja], g01 = gp[ia * WC2 + jb];
    float g10 = gp[ib * WC2 + ja], g11 = gp[ib * WC2 + jb];
    float gv = (1.f - wi) * ((1.f - wj) * g00 + wj * g01)
             + wi * ((1.f - wj) * g10 + wj * g11);
    float v = f1a[idx] + gv + b1[o];
    h[idx] = 0.5f * v * (1.f + erff(v * 0.70710678118654752f));
}

// ---------------- launch ----------------
extern "C" void kernel_launch(void* const* d_in, const int* in_sizes, int n_in,
                              void* d_out, int out_size) {
    const float* x        = (const float*)d_in[0];
    const float* w_qkv_l  = (const float*)d_in[1];
    const float* w_proj_l = (const float*)d_in[2];
    const float* b_proj_l = (const float*)d_in[3];
    const float* w_qkv_g  = (const float*)d_in[4];
    const float* w_proj_g = (const float*)d_in[5];
    const float* b_proj_g = (const float*)d_in[6];
    const float* w_f1     = (const float*)d_in[7];
    const float* b_f1     = (const float*)d_in[8];
    const float* w_f2     = (const float*)d_in[9];
    const float* b_f2     = (const float*)d_in[10];
    float* out = (float*)d_out;

    float *qkv_l, *attn_l, *local, *f1a, *h, *xc, *qkv_g, *attn_g, *gs, *gt;
    cudaGetSymbolAddress((void**)&qkv_l,  g_qkv_l);
    cudaGetSymbolAddress((void**)&attn_l, g_attn_l);
    cudaGetSymbolAddress((void**)&local,  g_local);
    cudaGetSymbolAddress((void**)&f1a,    g_f1a);
    cudaGetSymbolAddress((void**)&h,      g_hbuf);
    cudaGetSymbolAddress((void**)&xc,     g_xc);
    cudaGetSymbolAddress((void**)&qkv_g,  g_qkv_g);
    cudaGetSymbolAddress((void**)&attn_g, g_attn_g);
    cudaGetSymbolAddress((void**)&gs,     g_gs);
    cudaGetSymbolAddress((void**)&gt,     g_gt);

    dim3 blk(256);

    // local branch
    gemm_tc<<<dim3(SL / 128, 768 / 64, NB), blk>>>(w_qkv_l, x, qkv_l, nullptr, 768, 256, 256, SL);
    prenorm<<<dim3((SL + 127) / 128, 16, NB), dim3(128)>>>(qkv_l, SL);
    vcvt<<<dim3((NC * SL + 255) / 256, NB), blk>>>(qkv_l, SL);
    flash_tc<<<dim3(SL / 128, NHEADS, NB), blk>>>(qkv_l, attn_l, SL);
    gemm_tc<<<dim3(SL / 128, 4, NB), blk>>>(w_proj_l, attn_l, local, b_proj_l, 256, 256, 256, SL);

    // global branch (S=144)
    avgpool4<<<(NB * NC * SG + 255) / 256, blk>>>(x, xc);
    gemm_tc<<<dim3(2, 12, NB), blk>>>(w_qkv_g, xc, qkv_g, nullptr, 768, 256, 256, SG);
    prenorm<<<dim3((SG + 127) / 128, 16, NB), dim3(128)>>>(qkv_g, SG);
    vcvt<<<dim3((NC * SG + 255) / 256, NB), blk>>>(qkv_g, SG);
    flash_tc<<<dim3(2, NHEADS, NB), blk>>>(qkv_g, attn_g, SG);
    gemm_tc<<<dim3(2, 4, NB), blk>>>(w_proj_g, attn_g, gs, b_proj_g, 256, 256, 256, SG);

    // f1 split: local half at S=2304, global half at S=144 (upsample after conv)
    gemm_tc<<<dim3(SL / 128, 4, NB), blk>>>(w_f1, local, f1a, nullptr, 256, 256, 512, SL);
    gemm_tc<<<dim3(2, 4, NB), blk>>>(w_f1 + 256, gs, gt, nullptr, 256, 256, 512, SG);
    fuse_gelu<<<(NB * NC * SL + 255) / 256, blk>>>(f1a, gt, b_f1, h);

    // f2 -> output
    gemm_tc<<<dim3(SL / 128, 4, NB), blk>>>(w_f2, h, out, b_f2, 256, 256, 256, SL);
}

// round 5
// speedup vs baseline: 3.3688x; 1.3802x over previous
#include <cuda_runtime.h>
#include <math.h>

#define NB 4
#define NC 256
#define NH 48
#define NW 48
#define SL 2304
#define NHEADS 8
#define NHD 32
#define SG 144
#define HC2 12
#define WC2 12

// ---------------- scratch (no allocations allowed) ----------------
__device__ float g_qkv_l[NB * 3 * NC * SL];
__device__ float g_attn_l[NB * NC * SL];
__device__ float g_local [NB * NC * SL];
__device__ float g_f1a   [NB * NC * SL];
__device__ float g_hbuf  [NB * NC * SL];
__device__ float g_xc    [NB * NC * SG];
__device__ float g_qkv_g [NB * 3 * NC * SG];
__device__ float g_attn_g[NB * NC * SG];
__device__ float g_gs    [NB * NC * SG];
__device__ float g_gt    [NB * NC * SG];
__device__ unsigned g_vpk_l[NB * NC * SL / 2];   // bf16x2-packed V (local)
__device__ unsigned g_vpk_g[NB * NC * SG / 2];   // bf16x2-packed V (global branch)

// ---------------- helpers ----------------
__device__ __forceinline__ unsigned f2tf(float x) {
    unsigned r; asm("cvt.rna.tf32.f32 %0, %1;" : "=r"(r) : "f"(x)); return r;
}
__device__ __forceinline__ unsigned bfpack(float lo, float hi) {
    unsigned r; asm("cvt.rn.bf16x2.f32 %0, %1, %2;" : "=r"(r) : "f"(hi), "f"(lo)); return r;
}
__device__ __forceinline__ void mma8(float& c0, float& c1, float& c2, float& c3,
                                     unsigned a0, unsigned a1, unsigned a2, unsigned a3,
                                     unsigned b0, unsigned b1) {
    asm volatile("mma.sync.aligned.m16n8k8.row.col.f32.tf32.tf32.f32 "
                 "{%0,%1,%2,%3},{%4,%5,%6,%7},{%8,%9},{%0,%1,%2,%3};"
                 : "+f"(c0), "+f"(c1), "+f"(c2), "+f"(c3)
                 : "r"(a0), "r"(a1), "r"(a2), "r"(a3), "r"(b0), "r"(b1));
}
__device__ __forceinline__ void mma16bf(float& c0, float& c1, float& c2, float& c3,
                                        unsigned a0, unsigned a1, unsigned a2, unsigned a3,
                                        unsigned b0, unsigned b1) {
    asm volatile("mma.sync.aligned.m16n8k16.row.col.f32.bf16.bf16.f32 "
                 "{%0,%1,%2,%3},{%4,%5,%6,%7},{%8,%9},{%0,%1,%2,%3};"
                 : "+f"(c0), "+f"(c1), "+f"(c2), "+f"(c3)
                 : "r"(a0), "r"(a1), "r"(a2), "r"(a3), "r"(b0), "r"(b1));
}
__device__ __forceinline__ void cp16(void* dst, const void* src) {
    unsigned d = (unsigned)__cvta_generic_to_shared(dst);
    asm volatile("cp.async.cg.shared.global [%0], [%1], 16;" :: "r"(d), "l"(src));
}
// permute within 8-group so (w, w+4) become adjacent: w -> 2*(w&3) + (w>>2)
__device__ __forceinline__ int perm8(int w) {
    return (w & ~7) | (((w & 3) << 1) | ((w >> 2) & 1));
}

// ---------------- tf32 tensor-core GEMM, cp.async double-buffered ----------------
// Y[b,o,s] = sum_c W[o,c]*X[b,c,s] (+bias). block tile 64(o) x 128(s), k-chunk 16.
// 8 warps as 2(o) x 4(s), warp tile 32x32. raw f32 bits fed to tf32 mma (truncation).
__global__ __launch_bounds__(256) void gemm_tc(
    const float* __restrict__ Wm, const float* __restrict__ X,
    float* __restrict__ Y, const float* __restrict__ bias,
    int O, int Cin, int ldw, int Ssz)
{
    __shared__ __align__(16) float Ws[2][64][20];
    __shared__ __align__(16) float Xs[2][16][136];
    int tid = threadIdx.x;
    int wid = tid >> 5, lane = tid & 31;
    int g = lane >> 2, tc = lane & 3;
    int wm = wid & 1, wn = wid >> 1;
    int s0 = blockIdx.x * 128, o0 = blockIdx.y * 64, b = blockIdx.z;
    const float* Xb = X + (size_t)b * Cin * Ssz;

    int wrow = tid >> 2, wk = (tid & 3) << 2;

    float C[2][4][4];
    #pragma unroll
    for (int mt = 0; mt < 2; mt++)
        #pragma unroll
        for (int nt = 0; nt < 4; nt++)
            #pragma unroll
            for (int i = 0; i < 4; i++) C[mt][nt][i] = 0.f;

    int niter = Cin >> 4;

    // stage loader
    auto load_stage = [&](int st, int c0) {
        cp16(&Ws[st][wrow][wk], Wm + (size_t)(o0 + wrow) * ldw + c0 + wk);
        #pragma unroll
        for (int i = 0; i < 2; i++) {
            int idx = tid + i * 256;
            int k = idx >> 5, s4 = (idx & 31) << 2;
            if (s0 + s4 + 4 <= Ssz) {
                cp16(&Xs[st][k][s4], Xb + (size_t)(c0 + k) * Ssz + s0 + s4);
            } else {
                #pragma unroll
                for (int j = 0; j < 4; j++) {
                    float v = (s0 + s4 + j < Ssz) ? Xb[(size_t)(c0 + k) * Ssz + s0 + s4 + j] : 0.f;
                    Xs[st][k][s4 + j] = v;
                }
            }
        }
    };

    load_stage(0, 0);
    asm volatile("cp.async.commit_group;");

    for (int it = 0; it < niter; it++) {
        if (it + 1 < niter) load_stage((it + 1) & 1, (it + 1) << 4);
        asm volatile("cp.async.commit_group;");
        asm volatile("cp.async.wait_group 1;");
        __syncthreads();
        int st = it & 1;
        #pragma unroll
        for (int ks = 0; ks < 2; ks++) {
            int kk = ks * 8;
            unsigned a[2][4], bf[4][2];
            #pragma unroll
            for (int mt = 0; mt < 2; mt++) {
                int ob = wm * 32 + mt * 16;
                a[mt][0] = __float_as_uint(Ws[st][ob + g][kk + tc]);
                a[mt][1] = __float_as_uint(Ws[st][ob + g + 8][kk + tc]);
                a[mt][2] = __float_as_uint(Ws[st][ob + g][kk + tc + 4]);
                a[mt][3] = __float_as_uint(Ws[st][ob + g + 8][kk + tc + 4]);
            }
            #pragma unroll
            for (int nt = 0; nt < 4; nt++) {
                int sb = wn * 32 + nt * 8;
                bf[nt][0] = __float_as_uint(Xs[st][kk + tc][sb + g]);
                bf[nt][1] = __float_as_uint(Xs[st][kk + tc + 4][sb + g]);
            }
            #pragma unroll
            for (int mt = 0; mt < 2; mt++)
                #pragma unroll
                for (int nt = 0; nt < 4; nt++)
                    mma8(C[mt][nt][0], C[mt][nt][1], C[mt][nt][2], C[mt][nt][3],
                         a[mt][0], a[mt][1], a[mt][2], a[mt][3], bf[nt][0], bf[nt][1]);
        }
        __syncthreads();
    }

    float* Yb = Y + (size_t)b * O * Ssz;
    #pragma unroll
    for (int mt = 0; mt < 2; mt++)
        #pragma unroll
        for (int half = 0; half < 2; half++) {
            int o = o0 + wm * 32 + mt * 16 + g + half * 8;
            float bv = bias ? bias[o] : 0.f;
            #pragma unroll
            for (int nt = 0; nt < 4; nt++) {
                int s = s0 + wn * 32 + nt * 8 + 2 * tc;
                float v0 = C[mt][nt][half * 2 + 0] + bv;
                float v1 = C[mt][nt][half * 2 + 1] + bv;
                if (s + 1 < Ssz) *reinterpret_cast<float2*>(Yb + (size_t)o * Ssz + s) = make_float2(v0, v1);
                else if (s < Ssz) Yb[(size_t)o * Ssz + s] = v0;
            }
        }
}

// ---------------- prenorm: L2-normalize q (x scale) and k rows, cvt to tf32, in place ----------------
__global__ void prenorm(float* qkv, int Ssz) {
    int s = blockIdx.x * blockDim.x + threadIdx.x;
    if (s >= Ssz) return;
    int h = blockIdx.y & 7, isk = blockIdx.y >> 3, b = blockIdx.z;
    float* p = qkv + ((size_t)(b * 3 + isk) * NC + h * NHD) * Ssz + s;
    float v[32]; float ss = 0.f;
    #pragma unroll
    for (int d = 0; d < 32; d++) { v[d] = p[(size_t)d * Ssz]; ss += v[d] * v[d]; }
    float f = ((isk == 0) ? 0.17677669529663687f : 1.f) / fmaxf(sqrtf(ss), 1e-12f);
    #pragma unroll
    for (int d = 0; d < 32; d++) p[(size_t)d * Ssz] = __uint_as_float(f2tf(v[d] * f));
}

// ---------------- vpack: V section f32 -> bf16x2 packed words ----------------
// word (d, j) = pack(v[d][2j], v[d][2j+1]); layout [b][NC][Ssz/2]
__global__ void vpack(const float* __restrict__ qkv, unsigned* __restrict__ vpk, int Ssz) {
    int n = NC * (Ssz >> 1);
    int i = blockIdx.x * blockDim.x + threadIdx.x;
    if (i >= n) return;
    const float2 u = *reinterpret_cast<const float2*>(
        qkv + (size_t)(blockIdx.y * 3 + 2) * NC * Ssz + 2 * (size_t)i);
    vpk[(size_t)blockIdx.y * n + i] = bfpack(u.x, u.y);
}

// ---------------- flash attention: tf32 QK + bf16 PV, LDS.64 frag loads ----------------
// Br=128 (8 warps x 16 rows), Bc=64, d=32. grid (ceil(S/128), heads, B), block 256.
__global__ __launch_bounds__(256, 2) void flash_tc(
    const float* __restrict__ qkv, const unsigned* __restrict__ vpk,
    float* __restrict__ out, int Ssz)
{
    __shared__ __align__(16) unsigned Ks[64][36];   // [kv][d-permuted]
    __shared__ __align__(16) unsigned Vp[32][36];   // [d][kv-pair-permuted] bf16x2
    int tid = threadIdx.x, wid = tid >> 5, lane = tid & 31;
    int g = lane >> 2, tc = lane & 3;
    int qt = blockIdx.x, hh = blockIdx.y, bb = blockIdx.z;
    int s0 = qt * 128;
    int Ssz2 = Ssz >> 1;
    const float* qb = qkv + ((size_t)bb * 3 * NC + hh * NHD) * Ssz;
    const float* kb = qb + (size_t)NC * Ssz;
    const unsigned* vpb = vpk + ((size_t)bb * NC + hh * NHD) * Ssz2;

    // Q fragments in registers for all kv tiles
    unsigned qa[4][4];
    int r0 = s0 + wid * 16 + g, r1 = r0 + 8;
    #pragma unroll
    for (int ks = 0; ks < 4; ks++) {
        int d0 = ks * 8 + tc;
        qa[ks][0] = (r0 < Ssz) ? __float_as_uint(qb[(size_t)d0 * Ssz + r0]) : 0u;
        qa[ks][1] = (r1 < Ssz) ? __float_as_uint(qb[(size_t)d0 * Ssz + r1]) : 0u;
        qa[ks][2] = (r0 < Ssz) ? __float_as_uint(qb[(size_t)(d0 + 4) * Ssz + r0]) : 0u;
        qa[ks][3] = (r1 < Ssz) ? __float_as_uint(qb[(size_t)(d0 + 4) * Ssz + r1]) : 0u;
    }

    float m0 = -1e30f, m1 = -1e30f, l0 = 0.f, l1 = 0.f;
    float Oa[4][4];
    #pragma unroll
    for (int dt = 0; dt < 4; dt++)
        #pragma unroll
        for (int i = 0; i < 4; i++) Oa[dt][i] = 0.f;

    int nkt = (Ssz + 63) >> 6;
    for (int kt = 0; kt < nkt; kt++) {
        int k0 = kt * 64;
        __syncthreads();
        bool full = (k0 + 64 <= Ssz);
        // ---- K tile: 64 kv x 32 d (tf32), d permuted for LDS.64 frags ----
        #pragma unroll
        for (int i = 0; i < 2; i++) {
            int idx = tid + i * 256;           // 512 float4 slots
            int d = idx >> 4, c4 = (idx & 15) << 2;
            int dp = perm8(d);
            if (full) {
                float4 k4 = *reinterpret_cast<const float4*>(kb + (size_t)d * Ssz + k0 + c4);
                Ks[c4 + 0][dp] = __float_as_uint(k4.x); Ks[c4 + 1][dp] = __float_as_uint(k4.y);
                Ks[c4 + 2][dp] = __float_as_uint(k4.z); Ks[c4 + 3][dp] = __float_as_uint(k4.w);
            } else {
                #pragma unroll
                for (int j = 0; j < 4; j++) {
                    int sc = k0 + c4 + j;
                    Ks[c4 + j][dp] = (sc < Ssz) ? __float_as_uint(kb[(size_t)d * Ssz + sc]) : 0u;
                }
            }
        }
        // ---- V tile: bf16x2 words [d][32 pairs], pair-index permuted ----
        #pragma unroll
        for (int i = 0; i < 4; i++) {
            int idx = tid + i * 256;           // 1024 words
            int j = idx & 31, d = idx >> 5;
            unsigned w = 0u;
            if (full || (k0 + 2 * j < Ssz))
                w = vpb[(size_t)d * Ssz2 + (k0 >> 1) + j];
            Vp[d][perm8(j)] = w;
        }
        __syncthreads();

        // ---- S = Q K^T (tf32) ----
        float Sf[8][4];
        #pragma unroll
        for (int nt = 0; nt < 8; nt++)
            #pragma unroll
            for (int i = 0; i < 4; i++) Sf[nt][i] = 0.f;
        #pragma unroll
        for (int ks = 0; ks < 4; ks++)
            #pragma unroll
            for (int nt = 0; nt < 8; nt++) {
                uint2 kk2 = *reinterpret_cast<const uint2*>(&Ks[nt * 8 + g][ks * 8 + 2 * tc]);
                mma8(Sf[nt][0], Sf[nt][1], Sf[nt][2], Sf[nt][3],
                     qa[ks][0], qa[ks][1], qa[ks][2], qa[ks][3], kk2.x, kk2.y);
            }
        if (!full) {
            #pragma unroll
            for (int nt = 0; nt < 8; nt++) {
                int c = k0 + nt * 8 + 2 * tc;
                if (c     >= Ssz) { Sf[nt][0] = -1e30f; Sf[nt][2] = -1e30f; }
                if (c + 1 >= Ssz) { Sf[nt][1] = -1e30f; Sf[nt][3] = -1e30f; }
            }
        }

        // ---- warp-local online softmax (rows g and g+8) ----
        float t0 = -1e30f, t1 = -1e30f;
        #pragma unroll
        for (int nt = 0; nt < 8; nt++) {
            t0 = fmaxf(t0, fmaxf(Sf[nt][0], Sf[nt][1]));
            t1 = fmaxf(t1, fmaxf(Sf[nt][2], Sf[nt][3]));
        }
        t0 = fmaxf(t0, __shfl_xor_sync(0xffffffffu, t0, 1));
        t0 = fmaxf(t0, __shfl_xor_sync(0xffffffffu, t0, 2));
        t1 = fmaxf(t1, __shfl_xor_sync(0xffffffffu, t1, 1));
        t1 = fmaxf(t1, __shfl_xor_sync(0xffffffffu, t1, 2));
        float mn0 = fmaxf(m0, t0), mn1 = fmaxf(m1, t1);
        float co0 = __expf(m0 - mn0), co1 = __expf(m1 - mn1);
        m0 = mn0; m1 = mn1;
        float su0 = 0.f, su1 = 0.f;
        #pragma unroll
        for (int nt = 0; nt < 8; nt++) {
            Sf[nt][0] = __expf(Sf[nt][0] - mn0); su0 += Sf[nt][0];
            Sf[nt][1] = __expf(Sf[nt][1] - mn0); su0 += Sf[nt][1];
            Sf[nt][2] = __expf(Sf[nt][2] - mn1); su1 += Sf[nt][2];
            Sf[nt][3] = __expf(Sf[nt][3] - mn1); su1 += Sf[nt][3];
        }
        su0 += __shfl_xor_sync(0xffffffffu, su0, 1);
        su0 += __shfl_xor_sync(0xffffffffu, su0, 2);
        su1 += __shfl_xor_sync(0xffffffffu, su1, 1);
        su1 += __shfl_xor_sync(0xffffffffu, su1, 2);
        l0 = l0 * co0 + su0; l1 = l1 * co1 + su1;
        #pragma unroll
        for (int dt = 0; dt < 4; dt++) {
            Oa[dt][0] *= co0; Oa[dt][1] *= co0;
            Oa[dt][2] *= co1; Oa[dt][3] *= co1;
        }

        // ---- O += P V (bf16 m16n8k16, C-frag packs directly to A-frag) ----
        #pragma unroll
        for (int kb16 = 0; kb16 < 4; kb16++) {
            unsigned a0 = bfpack(Sf[2 * kb16][0],     Sf[2 * kb16][1]);
            unsigned a1 = bfpack(Sf[2 * kb16][2],     Sf[2 * kb16][3]);
            unsigned a2 = bfpack(Sf[2 * kb16 + 1][0], Sf[2 * kb16 + 1][1]);
            unsigned a3 = bfpack(Sf[2 * kb16 + 1][2], Sf[2 * kb16 + 1][3]);
            #pragma unroll
            for (int dt = 0; dt < 4; dt++) {
                uint2 vv2 = *reinterpret_cast<const uint2*>(&Vp[dt * 8 + g][kb16 * 8 + 2 * tc]);
                mma16bf(Oa[dt][0], Oa[dt][1], Oa[dt][2], Oa[dt][3],
                        a0, a1, a2, a3, vv2.x, vv2.y);
            }
        }
    }

    float i0 = 1.f / l0, i1 = 1.f / l1;
    float* ob = out + ((size_t)bb * NC + hh * NHD) * Ssz;
    #pragma unroll
    for (int dt = 0; dt < 4; dt++) {
        int d = dt * 8 + 2 * tc;
        if (r0 < Ssz) {
            ob[(size_t)d * Ssz + r0]       = Oa[dt][0] * i0;
            ob[(size_t)(d + 1) * Ssz + r0] = Oa[dt][1] * i0;
        }
        if (r1 < Ssz) {
            ob[(size_t)d * Ssz + r1]       = Oa[dt][2] * i1;
            ob[(size_t)(d + 1) * Ssz + r1] = Oa[dt][3] * i1;
        }
    }
}

// ---------------- 4x4 avg pool ----------------
__global__ void avgpool4(const float* __restrict__ x, float* __restrict__ xc) {
    int idx = blockIdx.x * blockDim.x + threadIdx.x;
    if (idx >= NB * NC * SG) return;
    int wc = idx % WC2;
    int hc = (idx / WC2) % HC2;
    int bc = idx / SG;
    const float* xp = x + (size_t)bc * (NH * NW) + (hc * 4) * NW + wc * 4;
    float s = 0.f;
    #pragma unroll
    for (int di = 0; di < 4; di++)
        #pragma unroll
        for (int dj = 0; dj < 4; dj++) s += xp[di * NW + dj];
    xc[idx] = s * (1.f / 16.f);
}

// ---------------- h = GELU(f1a + bilinear_up(gt) + b_f1) ----------------
__global__ void fuse_gelu(const float* __restrict__ f1a, const float* __restrict__ gt,
                          const float* __restrict__ b1, float* __restrict__ h) {
    int idx = blockIdx.x * blockDim.x + threadIdx.x;
    if (idx >= NB * NC * SL) return;
    int p = idx % SL;
    int bc = idx / SL;
    int o = bc % NC;
    int i = p / NW, j = p % NW;
    float si = (i + 0.5f) * 0.25f - 0.5f;
    float sj = (j + 0.5f) * 0.25f - 0.5f;
    float fi = floorf(si), fj = floorf(sj);
    float wi = si - fi, wj = sj - fj;
    int i0 = (int)fi, j0 = (int)fj;
    int ia = min(max(i0, 0), HC2 - 1), ib = min(max(i0 + 1, 0), HC2 - 1);
    int ja = min(max(j0, 0), WC2 - 1), jb = min(max(j0 + 1, 0), WC2 - 1);
    const float* gp = gt + (size_t)bc * SG;
    float g00 = gp[ia * WC2 + ja], g01 = gp[ia * WC2 + jb];
    float g10 = gp[ib * WC2 + ja], g11 = gp[ib * WC2 + jb];
    float gv = (1.f - wi) * ((1.f - wj) * g00 + wj * g01)
             + wi * ((1.f - wj) * g10 + wj * g11);
    float v = f1a[idx] + gv + b1[o];
    h[idx] = 0.5f * v * (1.f + erff(v * 0.70710678118654752f));
}

// ---------------- launch ----------------
extern "C" void kernel_launch(void* const* d_in, const int* in_sizes, int n_in,
                              void* d_out, int out_size) {
    const float* x        = (const float*)d_in[0];
    const float* w_qkv_l  = (const float*)d_in[1];
    const float* w_proj_l = (const float*)d_in[2];
    const float* b_proj_l = (const float*)d_in[3];
    const float* w_qkv_g  = (const float*)d_in[4];
    const float* w_proj_g = (const float*)d_in[5];
    const float* b_proj_g = (const float*)d_in[6];
    const float* w_f1     = (const float*)d_in[7];
    const float* b_f1     = (const float*)d_in[8];
    const float* w_f2     = (const float*)d_in[9];
    const float* b_f2     = (const float*)d_in[10];
    float* out = (float*)d_out;

    float *qkv_l, *attn_l, *local, *f1a, *h, *xc, *qkv_g, *attn_g, *gs, *gt;
    unsigned *vpk_l, *vpk_g;
    cudaGetSymbolAddress((void**)&qkv_l,  g_qkv_l);
    cudaGetSymbolAddress((void**)&attn_l, g_attn_l);
    cudaGetSymbolAddress((void**)&local,  g_local);
    cudaGetSymbolAddress((void**)&f1a,    g_f1a);
    cudaGetSymbolAddress((void**)&h,      g_hbuf);
    cudaGetSymbolAddress((void**)&xc,     g_xc);
    cudaGetSymbolAddress((void**)&qkv_g,  g_qkv_g);
    cudaGetSymbolAddress((void**)&attn_g, g_attn_g);
    cudaGetSymbolAddress((void**)&gs,     g_gs);
    cudaGetSymbolAddress((void**)&gt,     g_gt);
    cudaGetSymbolAddress((void**)&vpk_l,  g_vpk_l);
    cudaGetSymbolAddress((void**)&vpk_g,  g_vpk_g);

    dim3 blk(256);

    // local branch
    gemm_tc<<<dim3(SL / 128, 768 / 64, NB), blk>>>(w_qkv_l, x, qkv_l, nullptr, 768, 256, 256, SL);
    prenorm<<<dim3((SL + 127) / 128, 16, NB), dim3(128)>>>(qkv_l, SL);
    vpack<<<dim3((NC * SL / 2 + 255) / 256, NB), blk>>>(qkv_l, vpk_l, SL);
    flash_tc<<<dim3(SL / 128, NHEADS, NB), blk>>>(qkv_l, vpk_l, attn_l, SL);
    gemm_tc<<<dim3(SL / 128, 4, NB), blk>>>(w_proj_l, attn_l, local, b_proj_l, 256, 256, 256, SL);

    // global branch (S=144)
    avgpool4<<<(NB * NC * SG + 255) / 256, blk>>>(x, xc);
    gemm_tc<<<dim3(2, 12, NB), blk>>>(w_qkv_g, xc, qkv_g, nullptr, 768, 256, 256, SG);
    prenorm<<<dim3((SG + 127) / 128, 16, NB), dim3(128)>>>(qkv_g, SG);
    vpack<<<dim3((NC * SG / 2 + 255) / 256, NB), blk>>>(qkv_g, vpk_g, SG);
    flash_tc<<<dim3(2, NHEADS, NB), blk>>>(qkv_g, vpk_g, attn_g, SG);
    gemm_tc<<<dim3(2, 4, NB), blk>>>(w_proj_g, attn_g, gs, b_proj_g, 256, 256, 256, SG);

    // f1 split: local half at S=2304, global half at S=144 (upsample after conv)
    gemm_tc<<<dim3(SL / 128, 4, NB), blk>>>(w_f1, local, f1a, nullptr, 256, 256, 512, SL);
    gemm_tc<<<dim3(2, 4, NB), blk>>>(w_f1 + 256, gs, gt, nullptr, 256, 256, 512, SG);
    fuse_gelu<<<(NB * NC * SL + 255) / 256, blk>>>(f1a, gt, b_f1, h);

    // f2 -> output
    gemm_tc<<<dim3(SL / 128, 4, NB), blk>>>(w_f2, h, out, b_f2, 256, 256, 256, SL);
}

// round 6
// speedup vs baseline: 4.4025x; 1.3068x over previous
#include <cuda_runtime.h>
#include <math.h>

#define NB 4
#define NC 256
#define NH 48
#define NW 48
#define SL 2304
#define NHEADS 8
#define NHD 32
#define SG 144
#define HC2 12
#define WC2 12

// ---------------- scratch (no allocations allowed) ----------------
__device__ float g_qkv_l[NB * 3 * NC * SL];
__device__ float g_attn_l[NB * NC * SL];
__device__ float g_local [NB * NC * SL];
__device__ float g_f1a   [NB * NC * SL];
__device__ float g_hbuf  [NB * NC * SL];
__device__ float g_xc    [NB * NC * SG];
__device__ float g_qkv_g [NB * 3 * NC * SG];
__device__ float g_attn_g[NB * NC * SG];
__device__ float g_gs    [NB * NC * SG];
__device__ float g_gt    [NB * NC * SG];
__device__ unsigned g_vpk_l[NB * NC * SL / 2];        // bf16x2 V pairs [b][h*32+d][s/2]
__device__ unsigned g_vpk_g[NB * NC * SG / 2];
__device__ unsigned g_qpk_l[NB * NHEADS * 16 * SL];   // bf16x2 Q words [b][h][dpair][s]
__device__ unsigned g_kpk_l[NB * NHEADS * 16 * SL];   // bf16x2 K words [b][h][dpair][s]
__device__ unsigned g_qpk_g[NB * NHEADS * 16 * SG];
__device__ unsigned g_kpk_g[NB * NHEADS * 16 * SG];

// ---------------- helpers ----------------
__device__ __forceinline__ unsigned bfpack(float lo, float hi) {
    unsigned r; asm("cvt.rn.bf16x2.f32 %0, %1, %2;" : "=r"(r) : "f"(hi), "f"(lo)); return r;
}
__device__ __forceinline__ void mma8(float& c0, float& c1, float& c2, float& c3,
                                     unsigned a0, unsigned a1, unsigned a2, unsigned a3,
                                     unsigned b0, unsigned b1) {
    asm volatile("mma.sync.aligned.m16n8k8.row.col.f32.tf32.tf32.f32 "
                 "{%0,%1,%2,%3},{%4,%5,%6,%7},{%8,%9},{%0,%1,%2,%3};"
                 : "+f"(c0), "+f"(c1), "+f"(c2), "+f"(c3)
                 : "r"(a0), "r"(a1), "r"(a2), "r"(a3), "r"(b0), "r"(b1));
}
__device__ __forceinline__ void mma16bf(float& c0, float& c1, float& c2, float& c3,
                                        unsigned a0, unsigned a1, unsigned a2, unsigned a3,
                                        unsigned b0, unsigned b1) {
    asm volatile("mma.sync.aligned.m16n8k16.row.col.f32.bf16.bf16.f32 "
                 "{%0,%1,%2,%3},{%4,%5,%6,%7},{%8,%9},{%0,%1,%2,%3};"
                 : "+f"(c0), "+f"(c1), "+f"(c2), "+f"(c3)
                 : "r"(a0), "r"(a1), "r"(a2), "r"(a3), "r"(b0), "r"(b1));
}
__device__ __forceinline__ void cp16(void* dst, const void* src) {
    unsigned d = (unsigned)__cvta_generic_to_shared(dst);
    asm volatile("cp.async.cg.shared.global [%0], [%1], 16;" :: "r"(d), "l"(src));
}
// permute within 8-group so (w, w+4) become adjacent: w -> 2*(w&3) + (w>>2)
__device__ __forceinline__ int perm8(int w) {
    return (w & ~7) | (((w & 3) << 1) | ((w >> 2) & 1));
}

// ---------------- tf32 tensor-core GEMM, cp.async double-buffered ----------------
__global__ __launch_bounds__(256) void gemm_tc(
    const float* __restrict__ Wm, const float* __restrict__ X,
    float* __restrict__ Y, const float* __restrict__ bias,
    int O, int Cin, int ldw, int Ssz)
{
    __shared__ __align__(16) float Ws[2][64][20];
    __shared__ __align__(16) float Xs[2][16][136];
    int tid = threadIdx.x;
    int wid = tid >> 5, lane = tid & 31;
    int g = lane >> 2, tc = lane & 3;
    int wm = wid & 1, wn = wid >> 1;
    int s0 = blockIdx.x * 128, o0 = blockIdx.y * 64, b = blockIdx.z;
    const float* Xb = X + (size_t)b * Cin * Ssz;

    int wrow = tid >> 2, wk = (tid & 3) << 2;

    float C[2][4][4];
    #pragma unroll
    for (int mt = 0; mt < 2; mt++)
        #pragma unroll
        for (int nt = 0; nt < 4; nt++)
            #pragma unroll
            for (int i = 0; i < 4; i++) C[mt][nt][i] = 0.f;

    int niter = Cin >> 4;

    auto load_stage = [&](int st, int c0) {
        cp16(&Ws[st][wrow][wk], Wm + (size_t)(o0 + wrow) * ldw + c0 + wk);
        #pragma unroll
        for (int i = 0; i < 2; i++) {
            int idx = tid + i * 256;
            int k = idx >> 5, s4 = (idx & 31) << 2;
            if (s0 + s4 + 4 <= Ssz) {
                cp16(&Xs[st][k][s4], Xb + (size_t)(c0 + k) * Ssz + s0 + s4);
            } else {
                #pragma unroll
                for (int j = 0; j < 4; j++) {
                    float v = (s0 + s4 + j < Ssz) ? Xb[(size_t)(c0 + k) * Ssz + s0 + s4 + j] : 0.f;
                    Xs[st][k][s4 + j] = v;
                }
            }
        }
    };

    load_stage(0, 0);
    asm volatile("cp.async.commit_group;");

    for (int it = 0; it < niter; it++) {
        if (it + 1 < niter) load_stage((it + 1) & 1, (it + 1) << 4);
        asm volatile("cp.async.commit_group;");
        asm volatile("cp.async.wait_group 1;");
        __syncthreads();
        int st = it & 1;
        #pragma unroll
        for (int ks = 0; ks < 2; ks++) {
            int kk = ks * 8;
            unsigned a[2][4], bf[4][2];
            #pragma unroll
            for (int mt = 0; mt < 2; mt++) {
                int ob = wm * 32 + mt * 16;
                a[mt][0] = __float_as_uint(Ws[st][ob + g][kk + tc]);
                a[mt][1] = __float_as_uint(Ws[st][ob + g + 8][kk + tc]);
                a[mt][2] = __float_as_uint(Ws[st][ob + g][kk + tc + 4]);
                a[mt][3] = __float_as_uint(Ws[st][ob + g + 8][kk + tc + 4]);
            }
            #pragma unroll
            for (int nt = 0; nt < 4; nt++) {
                int sb = wn * 32 + nt * 8;
                bf[nt][0] = __float_as_uint(Xs[st][kk + tc][sb + g]);
                bf[nt][1] = __float_as_uint(Xs[st][kk + tc + 4][sb + g]);
            }
            #pragma unroll
            for (int mt = 0; mt < 2; mt++)
                #pragma unroll
                for (int nt = 0; nt < 4; nt++)
                    mma8(C[mt][nt][0], C[mt][nt][1], C[mt][nt][2], C[mt][nt][3],
                         a[mt][0], a[mt][1], a[mt][2], a[mt][3], bf[nt][0], bf[nt][1]);
        }
        __syncthreads();
    }

    float* Yb = Y + (size_t)b * O * Ssz;
    #pragma unroll
    for (int mt = 0; mt < 2; mt++)
        #pragma unroll
        for (int half = 0; half < 2; half++) {
            int o = o0 + wm * 32 + mt * 16 + g + half * 8;
            float bv = bias ? bias[o] : 0.f;
            #pragma unroll
            for (int nt = 0; nt < 4; nt++) {
                int s = s0 + wn * 32 + nt * 8 + 2 * tc;
                float v0 = C[mt][nt][half * 2 + 0] + bv;
                float v1 = C[mt][nt][half * 2 + 1] + bv;
                if (s + 1 < Ssz) *reinterpret_cast<float2*>(Yb + (size_t)o * Ssz + s) = make_float2(v0, v1);
                else if (s < Ssz) Yb[(size_t)o * Ssz + s] = v0;
            }
        }
}

// ---------------- prenorm: L2-normalize q (x scale) / k rows, emit packed bf16x2 words ----------------
// out layout: [b][h][dpair 16][Ssz] words; word dp = pack(v[2dp], v[2dp+1]).
// grid (ceil(S/128), 16, B), block 128. y: h = y&7, isk = y>>3.
__global__ void prenorm(const float* __restrict__ qkv,
                        unsigned* __restrict__ qpk, unsigned* __restrict__ kpk, int Ssz) {
    int s = blockIdx.x * blockDim.x + threadIdx.x;
    if (s >= Ssz) return;
    int h = blockIdx.y & 7, isk = blockIdx.y >> 3, b = blockIdx.z;
    const float* p = qkv + ((size_t)(b * 3 + isk) * NC + h * NHD) * Ssz + s;
    float v[32]; float ss = 0.f;
    #pragma unroll
    for (int d = 0; d < 32; d++) { v[d] = p[(size_t)d * Ssz]; ss += v[d] * v[d]; }
    float f = ((isk == 0) ? 0.17677669529663687f : 1.f) / fmaxf(sqrtf(ss), 1e-12f);
    unsigned* o = (isk ? kpk : qpk) + ((size_t)(b * NHEADS + h) * 16) * Ssz + s;
    #pragma unroll
    for (int dp = 0; dp < 16; dp++)
        o[(size_t)dp * Ssz] = bfpack(v[2 * dp] * f, v[2 * dp + 1] * f);
}

// ---------------- vpack: V section f32 -> bf16x2 pair words [b][h*32+d][s/2] ----------------
__global__ void vpack(const float* __restrict__ qkv, unsigned* __restrict__ vpk, int Ssz) {
    int n = NC * (Ssz >> 1);
    int i = blockIdx.x * blockDim.x + threadIdx.x;
    if (i >= n) return;
    const float2 u = *reinterpret_cast<const float2*>(
        qkv + (size_t)(blockIdx.y * 3 + 2) * NC * Ssz + 2 * (size_t)i);
    vpk[(size_t)blockIdx.y * n + i] = bfpack(u.x, u.y);
}

// ---------------- flash attention: all-bf16 m16n8k16, conflict-free smem (pitch 40) ----------------
// Br=128 (8 warps x 16 rows), Bc=64, d=32. grid (ceil(S/128), heads, B), block 256.
__global__ __launch_bounds__(256, 2) void flash_tc(
    const unsigned* __restrict__ qpk, const unsigned* __restrict__ kpk,
    const unsigned* __restrict__ vpk, float* __restrict__ out, int Ssz)
{
    __shared__ __align__(16) unsigned Ks2[64][40];  // [kv][dpair-perm] bf16x2; pitch 40: 8g banks
    __shared__ __align__(16) unsigned Vp [32][40];  // [d][kvpair-perm] bf16x2
    int tid = threadIdx.x, wid = tid >> 5, lane = tid & 31;
    int g = lane >> 2, tc = lane & 3;
    int qt = blockIdx.x, hh = blockIdx.y, bb = blockIdx.z;
    int s0 = qt * 128;
    int Ssz2 = Ssz >> 1;
    const unsigned* qpkb = qpk + ((size_t)(bb * NHEADS + hh) * 16) * Ssz;
    const unsigned* kpkb = kpk + ((size_t)(bb * NHEADS + hh) * 16) * Ssz;
    const unsigned* vpb  = vpk + ((size_t)bb * NC + hh * NHD) * Ssz2;

    // Q A-fragments (bf16x2 words), register-resident for all kv tiles
    unsigned qa[2][4];
    int r0 = s0 + wid * 16 + g, r1 = r0 + 8;
    #pragma unroll
    for (int ks = 0; ks < 2; ks++) {
        int dp = ks * 8 + tc;
        qa[ks][0] = (r0 < Ssz) ? qpkb[(size_t)dp * Ssz + r0] : 0u;
        qa[ks][1] = (r1 < Ssz) ? qpkb[(size_t)dp * Ssz + r1] : 0u;
        qa[ks][2] = (r0 < Ssz) ? qpkb[(size_t)(dp + 4) * Ssz + r0] : 0u;
        qa[ks][3] = (r1 < Ssz) ? qpkb[(size_t)(dp + 4) * Ssz + r1] : 0u;
    }

    float m0 = -1e30f, m1 = -1e30f, l0 = 0.f, l1 = 0.f;
    float Oa[4][4];
    #pragma unroll
    for (int dt = 0; dt < 4; dt++)
        #pragma unroll
        for (int i = 0; i < 4; i++) Oa[dt][i] = 0.f;

    int kvf = tid >> 2;          // K-fill role: kv row 0..63
    int dpb = tid & 3;

    int nkt = (Ssz + 63) >> 6;
    for (int kt = 0; kt < nkt; kt++) {
        int k0 = kt * 64;
        __syncthreads();
        bool full = (k0 + 64 <= Ssz);
        // ---- K tile: 64 kv x 16 dpair words ----
        #pragma unroll
        for (int i = 0; i < 4; i++) {
            int dp = dpb + 4 * i;
            unsigned w = 0u;
            if (full || (k0 + kvf < Ssz)) w = kpkb[(size_t)dp * Ssz + k0 + kvf];
            Ks2[kvf][perm8(dp)] = w;
        }
        // ---- V tile: 32 d x 32 pair words ----
        #pragma unroll
        for (int i = 0; i < 4; i++) {
            int idx = tid + i * 256;
            int j = idx & 31, d = idx >> 5;
            unsigned w = 0u;
            if (full || (k0 + 2 * j < Ssz)) w = vpb[(size_t)d * Ssz2 + (k0 >> 1) + j];
            Vp[d][perm8(j)] = w;
        }
        __syncthreads();

        // ---- S = Q K^T (bf16) ----
        float Sf[8][4];
        #pragma unroll
        for (int nt = 0; nt < 8; nt++)
            #pragma unroll
            for (int i = 0; i < 4; i++) Sf[nt][i] = 0.f;
        #pragma unroll
        for (int ks = 0; ks < 2; ks++)
            #pragma unroll
            for (int nt = 0; nt < 8; nt++) {
                uint2 kk2 = *reinterpret_cast<const uint2*>(&Ks2[nt * 8 + g][ks * 8 + 2 * tc]);
                mma16bf(Sf[nt][0], Sf[nt][1], Sf[nt][2], Sf[nt][3],
                        qa[ks][0], qa[ks][1], qa[ks][2], qa[ks][3], kk2.x, kk2.y);
            }
        if (!full) {
            #pragma unroll
            for (int nt = 0; nt < 8; nt++) {
                int c = k0 + nt * 8 + 2 * tc;
                if (c     >= Ssz) { Sf[nt][0] = -1e30f; Sf[nt][2] = -1e30f; }
                if (c + 1 >= Ssz) { Sf[nt][1] = -1e30f; Sf[nt][3] = -1e30f; }
            }
        }

        // ---- warp-local online softmax (rows r0, r1) ----
        float t0 = -1e30f, t1 = -1e30f;
        #pragma unroll
        for (int nt = 0; nt < 8; nt++) {
            t0 = fmaxf(t0, fmaxf(Sf[nt][0], Sf[nt][1]));
            t1 = fmaxf(t1, fmaxf(Sf[nt][2], Sf[nt][3]));
        }
        t0 = fmaxf(t0, __shfl_xor_sync(0xffffffffu, t0, 1));
        t0 = fmaxf(t0, __shfl_xor_sync(0xffffffffu, t0, 2));
        t1 = fmaxf(t1, __shfl_xor_sync(0xffffffffu, t1, 1));
        t1 = fmaxf(t1, __shfl_xor_sync(0xffffffffu, t1, 2));
        float mn0 = fmaxf(m0, t0), mn1 = fmaxf(m1, t1);
        float co0 = __expf(m0 - mn0), co1 = __expf(m1 - mn1);
        m0 = mn0; m1 = mn1;
        float su0 = 0.f, su1 = 0.f;
        #pragma unroll
        for (int nt = 0; nt < 8; nt++) {
            Sf[nt][0] = __expf(Sf[nt][0] - mn0); su0 += Sf[nt][0];
            Sf[nt][1] = __expf(Sf[nt][1] - mn0); su0 += Sf[nt][1];
            Sf[nt][2] = __expf(Sf[nt][2] - mn1); su1 += Sf[nt][2];
            Sf[nt][3] = __expf(Sf[nt][3] - mn1); su1 += Sf[nt][3];
        }
        su0 += __shfl_xor_sync(0xffffffffu, su0, 1);
        su0 += __shfl_xor_sync(0xffffffffu, su0, 2);
        su1 += __shfl_xor_sync(0xffffffffu, su1, 1);
        su1 += __shfl_xor_sync(0xffffffffu, su1, 2);
        l0 = l0 * co0 + su0; l1 = l1 * co1 + su1;
        #pragma unroll
        for (int dt = 0; dt < 4; dt++) {
            Oa[dt][0] *= co0; Oa[dt][1] *= co0;
            Oa[dt][2] *= co1; Oa[dt][3] *= co1;
        }

        // ---- O += P V (bf16; C-frag packs directly to A-frag) ----
        #pragma unroll
        for (int kb16 = 0; kb16 < 4; kb16++) {
            unsigned a0 = bfpack(Sf[2 * kb16][0],     Sf[2 * kb16][1]);
            unsigned a1 = bfpack(Sf[2 * kb16][2],     Sf[2 * kb16][3]);
            unsigned a2 = bfpack(Sf[2 * kb16 + 1][0], Sf[2 * kb16 + 1][1]);
            unsigned a3 = bfpack(Sf[2 * kb16 + 1][2], Sf[2 * kb16 + 1][3]);
            #pragma unroll
            for (int dt = 0; dt < 4; dt++) {
                uint2 vv2 = *reinterpret_cast<const uint2*>(&Vp[dt * 8 + g][kb16 * 8 + 2 * tc]);
                mma16bf(Oa[dt][0], Oa[dt][1], Oa[dt][2], Oa[dt][3],
                        a0, a1, a2, a3, vv2.x, vv2.y);
            }
        }
    }

    float i0 = 1.f / l0, i1 = 1.f / l1;
    float* ob = out + ((size_t)bb * NC + hh * NHD) * Ssz;
    #pragma unroll
    for (int dt = 0; dt < 4; dt++) {
        int d = dt * 8 + 2 * tc;
        if (r0 < Ssz) {
            ob[(size_t)d * Ssz + r0]       = Oa[dt][0] * i0;
            ob[(size_t)(d + 1) * Ssz + r0] = Oa[dt][1] * i0;
        }
        if (r1 < Ssz) {
            ob[(size_t)d * Ssz + r1]       = Oa[dt][2] * i1;
            ob[(size_t)(d + 1) * Ssz + r1] = Oa[dt][3] * i1;
        }
    }
}

// ---------------- 4x4 avg pool ----------------
__global__ void avgpool4(const float* __restrict__ x, float* __restrict__ xc) {
    int idx = blockIdx.x * blockDim.x + threadIdx.x;
    if (idx >= NB * NC * SG) return;
    int wc = idx % WC2;
    int hc = (idx / WC2) % HC2;
    int bc = idx / SG;
    const float* xp = x + (size_t)bc * (NH * NW) + (hc * 4) * NW + wc * 4;
    float s = 0.f;
    #pragma unroll
    for (int di = 0; di < 4; di++)
        #pragma unroll
        for (int dj = 0; dj < 4; dj++) s += xp[di * NW + dj];
    xc[idx] = s * (1.f / 16.f);
}

// ---------------- h = GELU(f1a + bilinear_up(gt) + b_f1) ----------------
__global__ void fuse_gelu(const float* __restrict__ f1a, const float* __restrict__ gt,
                          const float* __restrict__ b1, float* __restrict__ h) {
    int idx = blockIdx.x * blockDim.x + threadIdx.x;
    if (idx >= NB * NC * SL) return;
    int p = idx % SL;
    int bc = idx / SL;
    int o = bc % NC;
    int i = p / NW, j = p % NW;
    float si = (i + 0.5f) * 0.25f - 0.5f;
    float sj = (j + 0.5f) * 0.25f - 0.5f;
    float fi = floorf(si), fj = floorf(sj);
    float wi = si - fi, wj = sj - fj;
    int i0 = (int)fi, j0 = (int)fj;
    int ia = min(max(i0, 0), HC2 - 1), ib = min(max(i0 + 1, 0), HC2 - 1);
    int ja = min(max(j0, 0), WC2 - 1), jb = min(max(j0 + 1, 0), WC2 - 1);
    const float* gp = gt + (size_t)bc * SG;
    float g00 = gp[ia * WC2 + ja], g01 = gp[ia * WC2 + jb];
    float g10 = gp[ib * WC2 + ja], g11 = gp[ib * WC2 + jb];
    float gv = (1.f - wi) * ((1.f - wj) * g00 + wj * g01)
             + wi * ((1.f - wj) * g10 + wj * g11);
    float v = f1a[idx] + gv + b1[o];
    h[idx] = 0.5f * v * (1.f + erff(v * 0.70710678118654752f));
}

// ---------------- launch ----------------
extern "C" void kernel_launch(void* const* d_in, const int* in_sizes, int n_in,
                              void* d_out, int out_size) {
    const float* x        = (const float*)d_in[0];
    const float* w_qkv_l  = (const float*)d_in[1];
    const float* w_proj_l = (const float*)d_in[2];
    const float* b_proj_l = (const float*)d_in[3];
    const float* w_qkv_g  = (const float*)d_in[4];
    const float* w_proj_g = (const float*)d_in[5];
    const float* b_proj_g = (const float*)d_in[6];
    const float* w_f1     = (const float*)d_in[7];
    const float* b_f1     = (const float*)d_in[8];
    const float* w_f2     = (const float*)d_in[9];
    const float* b_f2     = (const float*)d_in[10];
    float* out = (float*)d_out;

    float *qkv_l, *attn_l, *local, *f1a, *h, *xc, *qkv_g, *attn_g, *gs, *gt;
    unsigned *vpk_l, *vpk_g, *qpk_l, *kpk_l, *qpk_g, *kpk_g;
    cudaGetSymbolAddress((void**)&qkv_l,  g_qkv_l);
    cudaGetSymbolAddress((void**)&attn_l, g_attn_l);
    cudaGetSymbolAddress((void**)&local,  g_local);
    cudaGetSymbolAddress((void**)&f1a,    g_f1a);
    cudaGetSymbolAddress((void**)&h,      g_hbuf);
    cudaGetSymbolAddress((void**)&xc,     g_xc);
    cudaGetSymbolAddress((void**)&qkv_g,  g_qkv_g);
    cudaGetSymbolAddress((void**)&attn_g, g_attn_g);
    cudaGetSymbolAddress((void**)&gs,     g_gs);
    cudaGetSymbolAddress((void**)&gt,     g_gt);
    cudaGetSymbolAddress((void**)&vpk_l,  g_vpk_l);
    cudaGetSymbolAddress((void**)&vpk_g,  g_vpk_g);
    cudaGetSymbolAddress((void**)&qpk_l,  g_qpk_l);
    cudaGetSymbolAddress((void**)&kpk_l,  g_kpk_l);
    cudaGetSymbolAddress((void**)&qpk_g,  g_qpk_g);
    cudaGetSymbolAddress((void**)&kpk_g,  g_kpk_g);

    dim3 blk(256);

    // local branch
    gemm_tc<<<dim3(SL / 128, 768 / 64, NB), blk>>>(w_qkv_l, x, qkv_l, nullptr, 768, 256, 256, SL);
    prenorm<<<dim3((SL + 127) / 128, 16, NB), dim3(128)>>>(qkv_l, qpk_l, kpk_l, SL);
    vpack<<<dim3((NC * SL / 2 + 255) / 256, NB), blk>>>(qkv_l, vpk_l, SL);
    flash_tc<<<dim3(SL / 128, NHEADS, NB), blk>>>(qpk_l, kpk_l, vpk_l, attn_l, SL);
    gemm_tc<<<dim3(SL / 128, 4, NB), blk>>>(w_proj_l, attn_l, local, b_proj_l, 256, 256, 256, SL);

    // global branch (S=144)
    avgpool4<<<(NB * NC * SG + 255) / 256, blk>>>(x, xc);
    gemm_tc<<<dim3(2, 12, NB), blk>>>(w_qkv_g, xc, qkv_g, nullptr, 768, 256, 256, SG);
    prenorm<<<dim3((SG + 127) / 128, 16, NB), dim3(128)>>>(qkv_g, qpk_g, kpk_g, SG);
    vpack<<<dim3((NC * SG / 2 + 255) / 256, NB), blk>>>(qkv_g, vpk_g, SG);
    flash_tc<<<dim3(2, NHEADS, NB), blk>>>(qpk_g, kpk_g, vpk_g, attn_g, SG);
    gemm_tc<<<dim3(2, 4, NB), blk>>>(w_proj_g, attn_g, gs, b_proj_g, 256, 256, 256, SG);

    // f1 split: local half at S=2304, global half at S=144 (upsample after conv)
    gemm_tc<<<dim3(SL / 128, 4, NB), blk>>>(w_f1, local, f1a, nullptr, 256, 256, 512, SL);
    gemm_tc<<<dim3(2, 4, NB), blk>>>(w_f1 + 256, gs, gt, nullptr, 256, 256, 512, SG);
    fuse_gelu<<<(NB * NC * SL + 255) / 256, blk>>>(f1a, gt, b_f1, h);

    // f2 -> output
    gemm_tc<<<dim3(SL / 128, 4, NB), blk>>>(w_f2, h, out, b_f2, 256, 256, 256, SL);
}